// round 11
// baseline (speedup 1.0000x reference)
#include <cuda_runtime.h>
#include <cuda_bf16.h>
#include <cstdint>

// Problem constants
#define BB 8
#define QQ 64
#define CC 512
#define DD 512
#define HH 256
#define EPSF 1e-5f
#define WOFF (BB * QQ * DD)

typedef unsigned long long ull;

__device__ float g_resq[BB * QQ * HH];        // [bq][h]
__device__ float g_rescT[BB * HH * CC];       // [b][h][c]

__device__ __forceinline__ float tanh_approx(float x) {
    float y;
    asm("tanh.approx.f32 %0, %1;" : "=f"(y) : "f"(x));
    return y;
}
__device__ __forceinline__ uint32_t cvt_tf32(float x) {
    uint32_t r; asm("cvt.rna.tf32.f32 %0, %1;" : "=r"(r) : "f"(x)); return r;
}
__device__ __forceinline__ uint32_t s2u(const void* p) {
    uint32_t a;
    asm("{ .reg .u64 t; cvta.to.shared.u64 t, %1; cvt.u32.u64 %0, t; }"
        : "=r"(a) : "l"(p));
    return a;
}
__device__ __forceinline__ void cp16(uint32_t s, const void* g) {
    asm volatile("cp.async.cg.shared.global [%0], [%1], 16;" :: "r"(s), "l"(g) : "memory");
}

#define MMA_TF32(c, a, b0, b1)                                            \
    asm volatile("mma.sync.aligned.m16n8k8.row.col.f32.tf32.tf32.f32 "    \
                 "{%0,%1,%2,%3}, {%4,%5,%6,%7}, {%8,%9}, {%0,%1,%2,%3};"  \
                 : "+f"((c)[0]), "+f"((c)[1]), "+f"((c)[2]), "+f"((c)[3]) \
                 : "r"((a)[0]), "r"((a)[1]), "r"((a)[2]), "r"((a)[3]),    \
                   "r"(b0), "r"(b1))

// ---- tc_gemms tiling: K-tile 64, 3 stages ----
#define LDA 72                       // 64 + 8 pad; 72 = 8 mod 32 -> conflict-free
#define ATILE_U (128 * LDA)          // 9216 u32
#define BTILE_U (64 * LDA)           // 4608 u32
#define STAGE_U (ATILE_U + BTILE_U)  // 13824 u32
#define NSTAGE 3
#define TCG_SMEM (NSTAGE * STAGE_U * 4)   // 165888 B

// ---------------------------------------------------------------------------
// A: tf32 mma.sync GEMMs, cp.async 3-stage pipeline, K-tile 64 (8 barriers
// instead of 16 -> half the barrier-latency exposure). 144 blocks x 256 thr.
//   blocks [0,128):  res_cT[b]: D[m=h(128)][n=c(64)] = Wc[h,:]·ctx[b][c,:]+bias
//   blocks [128,144): res_q:    D[m=bq(128)][n=h(64)] = q[bq,:]·Wq[h,:]
// k-slot permutation sigma=[0,2,4,6,1,3,5,7] on A and B -> LDS.64 fragments.
// ---------------------------------------------------------------------------
__global__ __launch_bounds__(256, 1)
void tc_gemms(const float* __restrict__ Wc,
              const float* __restrict__ Ctx,
              const float* __restrict__ bc,
              const float* __restrict__ Qm,
              const float* __restrict__ Wq)
{
    extern __shared__ uint32_t smem[];   // [stage][ A 128x72 | B 64x72 ]
    const uint32_t smem_b = s2u(smem);

    const int tid  = threadIdx.x;
    const int wid  = tid >> 5;
    const int lane = tid & 31;
    const int g    = lane >> 2;
    const int tg   = lane & 3;

    const int mbase = (wid & 3) * 32;    // 4 warps over M
    const int nbase = (wid >> 2) * 32;   // 2 warps over N

    // Block role
    const float *Ap, *Bp;
    const float* biasp = nullptr;
    float* outp;
    int ldo;
    const int blk = blockIdx.x;
    if (blk < 128) {
        const int b  = blk >> 4;
        const int ht = (blk >> 3) & 1;
        const int ct = blk & 7;
        Ap    = Wc + (size_t)(ht * 128) * DD;
        Bp    = Ctx + (size_t)b * CC * DD + (size_t)(ct * 64) * DD;
        outp  = g_rescT + (size_t)b * HH * CC + (size_t)(ht * 128) * CC + ct * 64;
        ldo   = CC;
        biasp = bc + ht * 128;
    } else {
        const int blk2 = blk - 128;
        const int mt = blk2 >> 2;
        const int nt = blk2 & 3;
        Ap   = Qm + (size_t)(mt * 128) * DD;
        Bp   = Wq + (size_t)(nt * 64) * DD;
        outp = g_resq + (size_t)(mt * 128) * HH + nt * 64;
        ldo  = HH;
    }

    // staging coords: A 2048 float4 (8/thread), B 1024 float4 (4/thread)
    int am[8], ak[8], bm[4], bk[4];
    #pragma unroll
    for (int i = 0; i < 8; i++) {
        const int f = tid + (i << 8);
        am[i] = f >> 4;                // 0..127
        ak[i] = (f & 15) << 2;         // 0..60
    }
    #pragma unroll
    for (int i = 0; i < 4; i++) {
        const int f = tid + (i << 8);
        bm[i] = f >> 4;                // 0..63
        bk[i] = (f & 15) << 2;
    }

    auto issue_stage = [&](int buf, int kt) {
        const uint32_t base = smem_b + buf * (STAGE_U * 4);
        #pragma unroll
        for (int i = 0; i < 8; i++)
            cp16(base + (am[i] * LDA + ak[i]) * 4,
                 Ap + (size_t)am[i] * DD + kt + ak[i]);
        #pragma unroll
        for (int i = 0; i < 4; i++)
            cp16(base + (ATILE_U + bm[i] * LDA + bk[i]) * 4,
                 Bp + (size_t)bm[i] * DD + kt + bk[i]);
        asm volatile("cp.async.commit_group;" ::: "memory");
    };

    float acc[2][4][4] = {};

    issue_stage(0, 0);
    issue_stage(1, 64);

    const int foff = 2 * tg;

    #pragma unroll 1
    for (int t = 0; t < 8; t++) {
        if (t < 6) {
            asm volatile("cp.async.wait_group 1;" ::: "memory");
        } else {
            asm volatile("cp.async.wait_group 0;" ::: "memory");
        }
        __syncthreads();

        if (t < 6) issue_stage((t + 2) % NSTAGE, (t + 2) * 64);

        const uint32_t* A_s = smem + (t % NSTAGE) * STAGE_U;
        const uint32_t* B_s = A_s + ATILE_U;
        #pragma unroll
        for (int ks = 0; ks < 8; ks++) {
            const int kc = ks * 8 + foff;
            uint32_t a[2][4];
            #pragma unroll
            for (int mt = 0; mt < 2; mt++) {
                const int rbase = (mbase + mt * 16 + g) * LDA + kc;
                const uint2 lo = *(const uint2*)&A_s[rbase];            // a0, a2
                const uint2 hi = *(const uint2*)&A_s[rbase + 8 * LDA];  // a1, a3
                a[mt][0] = lo.x; a[mt][2] = lo.y;
                a[mt][1] = hi.x; a[mt][3] = hi.y;
            }
            #pragma unroll
            for (int nt = 0; nt < 4; nt++) {
                const int bbase = (nbase + nt * 8 + g) * LDA + kc;
                const uint2 bv = *(const uint2*)&B_s[bbase];            // b0, b1
                MMA_TF32(acc[0][nt], a[0], bv.x, bv.y);
                MMA_TF32(acc[1][nt], a[1], bv.x, bv.y);
            }
        }
    }

    // Epilogue
    #pragma unroll
    for (int mt = 0; mt < 2; mt++) {
        const int row0 = mbase + mt * 16 + g;
        const int row1 = row0 + 8;
        const float bi0 = biasp ? biasp[row0] : 0.f;
        const float bi1 = biasp ? biasp[row1] : 0.f;
        #pragma unroll
        for (int nt = 0; nt < 4; nt++) {
            const int col = nbase + nt * 8 + tg * 2;
            float2 o0; o0.x = acc[mt][nt][0] + bi0; o0.y = acc[mt][nt][1] + bi0;
            float2 o1; o1.x = acc[mt][nt][2] + bi1; o1.y = acc[mt][nt][3] + bi1;
            *(float2*)(outp + (size_t)row0 * ldo + col) = o0;
            *(float2*)(outp + (size_t)row1 * ldo + col) = o1;
        }
    }
}

// ---------------------------------------------------------------------------
// B: logits (tanh over H) + softmax; writes weights to out[WOFF..].
// 1024 threads, grid 128. h-range split across halves, combine in smem.
// ---------------------------------------------------------------------------
__global__ __launch_bounds__(1024)
void logits_softmax(const float* __restrict__ Maskp,
                    const float* __restrict__ Wo,
                    const float* __restrict__ bo_p,
                    float* __restrict__ out)
{
    const int blk  = blockIdx.x;       // 0..127
    const int b    = blk >> 4;
    const int q0   = (blk & 15) * 4;
    const int tid  = threadIdx.x;
    const int c    = tid & 511;
    const int half = tid >> 9;

    __shared__ float4 sh_rq[HH];
    __shared__ float  sh_wo[HH];
    __shared__ float4 sh_acc[CC];
    __shared__ float  sh_part[4][16];
    __shared__ float  sh_tot[4];

    if (tid < HH) {
        float4 r;
        r.x = g_resq[(b * QQ + q0 + 0) * HH + tid];
        r.y = g_resq[(b * QQ + q0 + 1) * HH + tid];
        r.z = g_resq[(b * QQ + q0 + 2) * HH + tid];
        r.w = g_resq[(b * QQ + q0 + 3) * HH + tid];
        sh_rq[tid] = r;
        sh_wo[tid] = Wo[tid];
    }
    __syncthreads();

    float a0 = 0.f, a1 = 0.f, a2 = 0.f, a3 = 0.f;
    {
        const int hbase = half << 7;
        const float* rc = g_rescT + (size_t)b * HH * CC + (size_t)hbase * CC + c;
        #pragma unroll 8
        for (int h = 0; h < 128; h++) {
            const float  a  = rc[(size_t)h * CC];
            const float4 rq = sh_rq[hbase + h];
            const float  w  = sh_wo[hbase + h];
            a0 += w * tanh_approx(a + rq.x);
            a1 += w * tanh_approx(a + rq.y);
            a2 += w * tanh_approx(a + rq.z);
            a3 += w * tanh_approx(a + rq.w);
        }
    }
    if (half == 0) {
        sh_acc[c] = make_float4(a0, a1, a2, a3);
    }
    __syncthreads();

    float e0, e1, e2, e3;
    if (half == 1) {
        const float4 p = sh_acc[c];
        const float bo = __ldg(bo_p);
        const float m  = Maskp[b * CC + c];
        e0 = m * __expf(a0 + p.x + bo);
        e1 = m * __expf(a1 + p.y + bo);
        e2 = m * __expf(a2 + p.z + bo);
        e3 = m * __expf(a3 + p.w + bo);

        float s0 = e0, s1 = e1, s2 = e2, s3 = e3;
        #pragma unroll
        for (int off = 16; off > 0; off >>= 1) {
            s0 += __shfl_xor_sync(0xffffffffu, s0, off);
            s1 += __shfl_xor_sync(0xffffffffu, s1, off);
            s2 += __shfl_xor_sync(0xffffffffu, s2, off);
            s3 += __shfl_xor_sync(0xffffffffu, s3, off);
        }
        const int lane = tid & 31, w2 = (tid >> 5) & 15;
        if (lane == 0) {
            sh_part[0][w2] = s0; sh_part[1][w2] = s1;
            sh_part[2][w2] = s2; sh_part[3][w2] = s3;
        }
    }
    __syncthreads();
    if (tid < 4) {
        float t = 0.f;
        #pragma unroll
        for (int i = 0; i < 16; i++) t += sh_part[tid][i];
        sh_tot[tid] = 1.f / (t + EPSF);
    }
    __syncthreads();

    if (half == 1) {
        out[WOFF + (b * QQ + q0 + 0) * CC + c] = e0 * sh_tot[0];
        out[WOFF + (b * QQ + q0 + 1) * CC + c] = e1 * sh_tot[1];
        out[WOFF + (b * QQ + q0 + 2) * CC + c] = e2 * sh_tot[2];
        out[WOFF + (b * QQ + q0 + 3) * CC + c] = e3 * sh_tot[3];
    }
}

// ---------------------------------------------------------------------------
// C: output[bq][d] = sum_c weights[bq][c] * ctx[b][c][d] via tf32 mma.sync.
// Block: 64q x 64d, K=c=512 in 16 tiles of 32, double-buffered smem,
// RNA tf32 staging (zero-mean rounding: output is final answer).
// grid = 8 b x 8 d-tiles = 64 blocks, 256 threads (2 warps over M, 4 over N).
// B (= ctx [c][d] = [k][n]) fragments gathered by scalar LDS at the SAME
// permuted k-positions {2tg, 2tg+1} as A -> dot product invariant.
// ---------------------------------------------------------------------------
#define OLDK 40                      // A row: 32 k + 8 pad
#define OLDN 68                      // B row: 64 n + 4 pad
#define OA_U (64 * OLDK)             // 2560 u32
#define OB_U (32 * OLDN)             // 2176 u32
#define OSTAGE_U (OA_U + OB_U)       // 4736 u32

__global__ __launch_bounds__(256)
void out_mma(const float* __restrict__ Ctx,
             const float* __restrict__ Wgt,   // = out + WOFF
             float* __restrict__ out)
{
    __shared__ uint32_t smem[2 * OSTAGE_U];   // 37888 B

    const int blk = blockIdx.x;        // 0..63
    const int b   = blk >> 3;
    const int d0  = (blk & 7) * 64;

    const int tid  = threadIdx.x;
    const int wid  = tid >> 5;
    const int lane = tid & 31;
    const int g    = lane >> 2;
    const int tg   = lane & 3;

    const int mbase = (wid & 1) * 32;  // 2 warps over M (q)
    const int nbase = (wid >> 1) * 16; // 4 warps over N (d)

    const float* Wp = Wgt + (size_t)b * QQ * CC;
    const float* Cp = Ctx + (size_t)b * CC * DD + d0;

    // staging coords: A 512 f4 (2/thread), B 512 f4 (2/thread)
    int aq[2], ac[2], bc_[2], bd[2];
    #pragma unroll
    for (int i = 0; i < 2; i++) {
        const int f = tid + (i << 8);
        aq[i]  = f >> 3;               // 0..63 (q row)
        ac[i]  = (f & 7) << 2;         // 0..28 (c offset)
        bc_[i] = f >> 4;               // 0..31 (c row)
        bd[i]  = (f & 15) << 2;        // 0..60 (d offset)
    }

    auto stage = [&](int buf, int kt) {
        uint32_t* A_s = smem + buf * OSTAGE_U;
        uint32_t* B_s = A_s + OA_U;
        #pragma unroll
        for (int i = 0; i < 2; i++) {
            const float4 w = *(const float4*)&Wp[(size_t)aq[i] * CC + kt + ac[i]];
            uint32_t addr = s2u(A_s + aq[i] * OLDK + ac[i]);
            asm volatile("st.shared.v4.b32 [%0], {%1,%2,%3,%4};"
                         :: "r"(addr), "r"(cvt_tf32(w.x)), "r"(cvt_tf32(w.y)),
                            "r"(cvt_tf32(w.z)), "r"(cvt_tf32(w.w)) : "memory");
            const float4 cvv = *(const float4*)&Cp[(size_t)(kt + bc_[i]) * DD + bd[i]];
            uint32_t baddr = s2u(B_s + bc_[i] * OLDN + bd[i]);
            asm volatile("st.shared.v4.b32 [%0], {%1,%2,%3,%4};"
                         :: "r"(baddr), "r"(cvt_tf32(cvv.x)), "r"(cvt_tf32(cvv.y)),
                            "r"(cvt_tf32(cvv.z)), "r"(cvt_tf32(cvv.w)) : "memory");
        }
    };

    float acc[2][2][4] = {};

    stage(0, 0);
    __syncthreads();

    #pragma unroll 1
    for (int t = 0; t < 16; t++) {
        const int buf = t & 1;
        // prefetch next into registers implicitly via stage() after compute? ->
        // simple: compute current, then stage next (double buffer, one sync).
        const uint32_t* A_s = smem + buf * OSTAGE_U;
        const uint32_t* B_s = A_s + OA_U;
        #pragma unroll
        for (int ks = 0; ks < 4; ks++) {
            const int kc = ks * 8 + 2 * tg;
            uint32_t a[2][4];
            #pragma unroll
            for (int mt = 0; mt < 2; mt++) {
                const int rbase = (mbase + mt * 16 + g) * OLDK + kc;
                const uint2 lo = *(const uint2*)&A_s[rbase];
                const uint2 hi = *(const uint2*)&A_s[rbase + 8 * OLDK];
                a[mt][0] = lo.x; a[mt][2] = lo.y;
                a[mt][1] = hi.x; a[mt][3] = hi.y;
            }
            #pragma unroll
            for (int nt = 0; nt < 2; nt++) {
                const int col = nbase + nt * 8 + g;
                const uint32_t b0 = B_s[(kc + 0) * OLDN + col];
                const uint32_t b1 = B_s[(kc + 1) * OLDN + col];
                MMA_TF32(acc[0][nt], a[0], b0, b1);
                MMA_TF32(acc[1][nt], a[1], b0, b1);
            }
        }
        if (t < 15) {
            stage(buf ^ 1, (t + 1) * 32);
        }
        __syncthreads();
    }

    // Epilogue: D[q][d]
    #pragma unroll
    for (int mt = 0; mt < 2; mt++) {
        const int row0 = mbase + mt * 16 + g;
        const int row1 = row0 + 8;
        #pragma unroll
        for (int nt = 0; nt < 2; nt++) {
            const int col = d0 + nbase + nt * 8 + tg * 2;
            float2 o0; o0.x = acc[mt][nt][0]; o0.y = acc[mt][nt][1];
            float2 o1; o1.x = acc[mt][nt][2]; o1.y = acc[mt][nt][3];
            *(float2*)&out[(size_t)(b * QQ + row0) * DD + col] = o0;
            *(float2*)&out[(size_t)(b * QQ + row1) * DD + col] = o1;
        }
    }
}

// ---------------------------------------------------------------------------
extern "C" void kernel_launch(void* const* d_in, const int* in_sizes, int n_in,
                              void* d_out, int out_size)
{
    const float* query   = (const float*)d_in[0];
    const float* context = (const float*)d_in[1];
    const float* mask    = (const float*)d_in[2];
    const float* W_c     = (const float*)d_in[3];
    const float* b_c     = (const float*)d_in[4];
    const float* W_q     = (const float*)d_in[5];
    const float* W_o     = (const float*)d_in[6];
    const float* b_o     = (const float*)d_in[7];
    float* out = (float*)d_out;

    cudaFuncSetAttribute(tc_gemms, cudaFuncAttributeMaxDynamicSharedMemorySize,
                         TCG_SMEM);

    tc_gemms<<<144, 256, TCG_SMEM>>>(W_c, context, b_c, query, W_q);
    logits_softmax<<<128, 1024>>>(mask, W_o, b_o, out);
    out_mma<<<64, 256>>>(context, out + WOFF, out);
}

// round 12
// speedup vs baseline: 1.0396x; 1.0396x over previous
#include <cuda_runtime.h>
#include <cuda_bf16.h>
#include <cstdint>

// Problem constants
#define BB 8
#define QQ 64
#define CC 512
#define DD 512
#define HH 256
#define EPSF 1e-5f
#define WOFF (BB * QQ * DD)

typedef unsigned long long ull;

__device__ float g_resq[BB * QQ * HH];        // [bq][h]
__device__ float g_rescT[BB * HH * CC];       // [b][h][c]

__device__ __forceinline__ float tanh_approx(float x) {
    float y;
    asm("tanh.approx.f32 %0, %1;" : "=f"(y) : "f"(x));
    return y;
}
__device__ __forceinline__ ull pack2(float x) {
    ull r; asm("mov.b64 %0, {%1, %1};" : "=l"(r) : "f"(x)); return r;
}
__device__ __forceinline__ void fma2(ull& d, ull a, ull b) {
    asm("fma.rn.f32x2 %0, %1, %2, %0;" : "+l"(d) : "l"(a), "l"(b));
}
__device__ __forceinline__ float2 unpack2(ull v) {
    float2 r; asm("mov.b64 {%0, %1}, %2;" : "=f"(r.x), "=f"(r.y) : "l"(v)); return r;
}
__device__ __forceinline__ uint32_t s2u(const void* p) {
    uint32_t a;
    asm("{ .reg .u64 t; cvta.to.shared.u64 t, %1; cvt.u32.u64 %0, t; }"
        : "=r"(a) : "l"(p));
    return a;
}
__device__ __forceinline__ void cp16(uint32_t s, const void* g) {
    asm volatile("cp.async.cg.shared.global [%0], [%1], 16;" :: "r"(s), "l"(g) : "memory");
}

#define MMA_TF32(c, a, b0, b1)                                            \
    asm volatile("mma.sync.aligned.m16n8k8.row.col.f32.tf32.tf32.f32 "    \
                 "{%0,%1,%2,%3}, {%4,%5,%6,%7}, {%8,%9}, {%0,%1,%2,%3};"  \
                 : "+f"((c)[0]), "+f"((c)[1]), "+f"((c)[2]), "+f"((c)[3]) \
                 : "r"((a)[0]), "r"((a)[1]), "r"((a)[2]), "r"((a)[3]),    \
                   "r"(b0), "r"(b1))

// ---- tc_gemms tiling: K-tile 64, 3 stages ----
#define LDA 72                       // 64 + 8 pad
#define ATILE_U (128 * LDA)          // 9216 u32
#define BTILE_U (64 * LDA)           // 4608 u32
#define STAGE_U (ATILE_U + BTILE_U)  // 13824 u32
#define NSTAGE 3
#define TCG_SMEM (NSTAGE * STAGE_U * 4)   // 165888 B

// ---------------------------------------------------------------------------
// A: tf32 mma.sync GEMMs, cp.async 3-stage pipeline, K-tile 64 (8 barriers).
// 144 blocks x 256 threads.
//   blocks [0,128):  res_cT[b]: D[m=h(128)][n=c(64)] = Wc[h,:]·ctx[b][c,:]+bias
//   blocks [128,144): res_q:    D[m=bq(128)][n=h(64)] = q[bq,:]·Wq[h,:]
// k-slot permutation sigma=[0,2,4,6,1,3,5,7] on A and B -> LDS.64 fragments.
// ---------------------------------------------------------------------------
__global__ __launch_bounds__(256, 1)
void tc_gemms(const float* __restrict__ Wc,
              const float* __restrict__ Ctx,
              const float* __restrict__ bc,
              const float* __restrict__ Qm,
              const float* __restrict__ Wq)
{
    extern __shared__ uint32_t smem[];   // [stage][ A 128x72 | B 64x72 ]
    const uint32_t smem_b = s2u(smem);

    const int tid  = threadIdx.x;
    const int wid  = tid >> 5;
    const int lane = tid & 31;
    const int g    = lane >> 2;
    const int tg   = lane & 3;

    const int mbase = (wid & 3) * 32;    // 4 warps over M
    const int nbase = (wid >> 2) * 32;   // 2 warps over N

    // Block role
    const float *Ap, *Bp;
    const float* biasp = nullptr;
    float* outp;
    int ldo;
    const int blk = blockIdx.x;
    if (blk < 128) {
        const int b  = blk >> 4;
        const int ht = (blk >> 3) & 1;
        const int ct = blk & 7;
        Ap    = Wc + (size_t)(ht * 128) * DD;
        Bp    = Ctx + (size_t)b * CC * DD + (size_t)(ct * 64) * DD;
        outp  = g_rescT + (size_t)b * HH * CC + (size_t)(ht * 128) * CC + ct * 64;
        ldo   = CC;
        biasp = bc + ht * 128;
    } else {
        const int blk2 = blk - 128;
        const int mt = blk2 >> 2;
        const int nt = blk2 & 3;
        Ap   = Qm + (size_t)(mt * 128) * DD;
        Bp   = Wq + (size_t)(nt * 64) * DD;
        outp = g_resq + (size_t)(mt * 128) * HH + nt * 64;
        ldo  = HH;
    }

    // staging coords: A 2048 float4 (8/thread), B 1024 float4 (4/thread)
    int am[8], ak[8], bm[4], bk[4];
    #pragma unroll
    for (int i = 0; i < 8; i++) {
        const int f = tid + (i << 8);
        am[i] = f >> 4;
        ak[i] = (f & 15) << 2;
    }
    #pragma unroll
    for (int i = 0; i < 4; i++) {
        const int f = tid + (i << 8);
        bm[i] = f >> 4;
        bk[i] = (f & 15) << 2;
    }

    auto issue_stage = [&](int buf, int kt) {
        const uint32_t base = smem_b + buf * (STAGE_U * 4);
        #pragma unroll
        for (int i = 0; i < 8; i++)
            cp16(base + (am[i] * LDA + ak[i]) * 4,
                 Ap + (size_t)am[i] * DD + kt + ak[i]);
        #pragma unroll
        for (int i = 0; i < 4; i++)
            cp16(base + (ATILE_U + bm[i] * LDA + bk[i]) * 4,
                 Bp + (size_t)bm[i] * DD + kt + bk[i]);
        asm volatile("cp.async.commit_group;" ::: "memory");
    };

    float acc[2][4][4] = {};

    issue_stage(0, 0);
    issue_stage(1, 64);

    const int foff = 2 * tg;

    #pragma unroll 1
    for (int t = 0; t < 8; t++) {
        if (t < 6) {
            asm volatile("cp.async.wait_group 1;" ::: "memory");
        } else {
            asm volatile("cp.async.wait_group 0;" ::: "memory");
        }
        __syncthreads();

        if (t < 6) issue_stage((t + 2) % NSTAGE, (t + 2) * 64);

        const uint32_t* A_s = smem + (t % NSTAGE) * STAGE_U;
        const uint32_t* B_s = A_s + ATILE_U;
        #pragma unroll
        for (int ks = 0; ks < 8; ks++) {
            const int kc = ks * 8 + foff;
            uint32_t a[2][4];
            #pragma unroll
            for (int mt = 0; mt < 2; mt++) {
                const int rbase = (mbase + mt * 16 + g) * LDA + kc;
                const uint2 lo = *(const uint2*)&A_s[rbase];            // a0, a2
                const uint2 hi = *(const uint2*)&A_s[rbase + 8 * LDA];  // a1, a3
                a[mt][0] = lo.x; a[mt][2] = lo.y;
                a[mt][1] = hi.x; a[mt][3] = hi.y;
            }
            #pragma unroll
            for (int nt = 0; nt < 4; nt++) {
                const int bbase = (nbase + nt * 8 + g) * LDA + kc;
                const uint2 bv = *(const uint2*)&B_s[bbase];            // b0, b1
                MMA_TF32(acc[0][nt], a[0], bv.x, bv.y);
                MMA_TF32(acc[1][nt], a[1], bv.x, bv.y);
            }
        }
    }

    // Epilogue
    #pragma unroll
    for (int mt = 0; mt < 2; mt++) {
        const int row0 = mbase + mt * 16 + g;
        const int row1 = row0 + 8;
        const float bi0 = biasp ? biasp[row0] : 0.f;
        const float bi1 = biasp ? biasp[row1] : 0.f;
        #pragma unroll
        for (int nt = 0; nt < 4; nt++) {
            const int col = nbase + nt * 8 + tg * 2;
            float2 o0; o0.x = acc[mt][nt][0] + bi0; o0.y = acc[mt][nt][1] + bi0;
            float2 o1; o1.x = acc[mt][nt][2] + bi1; o1.y = acc[mt][nt][3] + bi1;
            *(float2*)(outp + (size_t)row0 * ldo + col) = o0;
            *(float2*)(outp + (size_t)row1 * ldo + col) = o1;
        }
    }
}

// ---------------------------------------------------------------------------
// B: logits (tanh over H) + softmax; writes weights to out[WOFF..].
// q-tile 2 -> grid 256 (fills all 148 SMs; MUFU floor drops ~14%).
// 1024 threads: c = tid&511, h-range split across halves, combine in smem.
// ---------------------------------------------------------------------------
__global__ __launch_bounds__(1024)
void logits_softmax(const float* __restrict__ Maskp,
                    const float* __restrict__ Wo,
                    const float* __restrict__ bo_p,
                    float* __restrict__ out)
{
    const int blk  = blockIdx.x;       // 0..255
    const int b    = blk >> 5;
    const int q0   = (blk & 31) * 2;
    const int tid  = threadIdx.x;
    const int c    = tid & 511;
    const int half = tid >> 9;

    __shared__ float2 sh_rq[HH];
    __shared__ float  sh_wo[HH];
    __shared__ float2 sh_acc[CC];
    __shared__ float  sh_part[2][16];
    __shared__ float  sh_tot[2];

    if (tid < HH) {
        float2 r;
        r.x = g_resq[(b * QQ + q0 + 0) * HH + tid];
        r.y = g_resq[(b * QQ + q0 + 1) * HH + tid];
        sh_rq[tid] = r;
        sh_wo[tid] = Wo[tid];
    }
    __syncthreads();

    float a0 = 0.f, a1 = 0.f;
    {
        const int hbase = half << 7;
        const float* rc = g_rescT + (size_t)b * HH * CC + (size_t)hbase * CC + c;
        #pragma unroll 8
        for (int h = 0; h < 128; h++) {
            const float  a  = rc[(size_t)h * CC];
            const float2 rq = sh_rq[hbase + h];
            const float  w  = sh_wo[hbase + h];
            a0 += w * tanh_approx(a + rq.x);
            a1 += w * tanh_approx(a + rq.y);
        }
    }
    if (half == 0) {
        sh_acc[c] = make_float2(a0, a1);
    }
    __syncthreads();

    float e0, e1;
    if (half == 1) {
        const float2 p = sh_acc[c];
        const float bo = __ldg(bo_p);
        const float m  = Maskp[b * CC + c];
        e0 = m * __expf(a0 + p.x + bo);
        e1 = m * __expf(a1 + p.y + bo);

        float s0 = e0, s1 = e1;
        #pragma unroll
        for (int off = 16; off > 0; off >>= 1) {
            s0 += __shfl_xor_sync(0xffffffffu, s0, off);
            s1 += __shfl_xor_sync(0xffffffffu, s1, off);
        }
        const int lane = tid & 31, w2 = (tid >> 5) & 15;
        if (lane == 0) {
            sh_part[0][w2] = s0; sh_part[1][w2] = s1;
        }
    }
    __syncthreads();
    if (tid < 2) {
        float t = 0.f;
        #pragma unroll
        for (int i = 0; i < 16; i++) t += sh_part[tid][i];
        sh_tot[tid] = 1.f / (t + EPSF);
    }
    __syncthreads();

    if (half == 1) {
        out[WOFF + (b * QQ + q0 + 0) * CC + c] = e0 * sh_tot[0];
        out[WOFF + (b * QQ + q0 + 1) * CC + c] = e1 * sh_tot[1];
    }
}

// ---------------------------------------------------------------------------
// C: output[bq][d] = sum_c weights[bq][c] * ctx[b][c][d]
// Tiled GEMM: 64q x 32d per block, K=512, double-buffered, f32x2 FMA.
// grid = 8 b * 16 d-tiles = 128 blocks, 256 threads. (R10 version — fp32 exact)
// ---------------------------------------------------------------------------
__global__ __launch_bounds__(256)
void out_gemm(const float* __restrict__ Ctx,
              const float* __restrict__ Wgt,
              float* __restrict__ out)
{
    const int blk = blockIdx.x;        // 0..127
    const int b   = blk >> 4;
    const int d0  = (blk & 15) * 32;
    const int tid = threadIdx.x;
    const int ty  = tid >> 4;
    const int tx  = tid & 15;

    __shared__ float Ws[2][16][68];
    __shared__ float Cs[2][16][34];

    const float* Wp = Wgt + (size_t)b * QQ * CC;
    const float* Cp = Ctx + (size_t)b * CC * DD;

    const int qr = tid >> 2;
    const int cg = tid & 3;
    const int cl = tid >> 4;
    const int dl = (tid & 15) * 2;

    ull acc[4] = {};

    {
        float4 w4 = *(const float4*)&Wp[qr * CC + cg * 4];
        Ws[0][cg*4+0][qr] = w4.x; Ws[0][cg*4+1][qr] = w4.y;
        Ws[0][cg*4+2][qr] = w4.z; Ws[0][cg*4+3][qr] = w4.w;
        float2 c2 = *(const float2*)&Cp[(size_t)cl * DD + d0 + dl];
        Cs[0][cl][dl] = c2.x; Cs[0][cl][dl+1] = c2.y;
    }
    __syncthreads();

    int buf = 0;
    for (int c0 = 16; c0 <= CC; c0 += 16) {
        float4 nw; float2 nc;
        const bool more = (c0 < CC);
        if (more) {
            nw = *(const float4*)&Wp[qr * CC + c0 + cg * 4];
            nc = *(const float2*)&Cp[(size_t)(c0 + cl) * DD + d0 + dl];
        }

        #pragma unroll
        for (int cc = 0; cc < 16; cc++) {
            float4 w4 = *(const float4*)&Ws[buf][cc][ty * 4];
            ull cv = *(const ull*)&Cs[buf][cc][tx * 2];
            fma2(acc[0], pack2(w4.x), cv);
            fma2(acc[1], pack2(w4.y), cv);
            fma2(acc[2], pack2(w4.z), cv);
            fma2(acc[3], pack2(w4.w), cv);
        }

        if (more) {
            const int nbuf = buf ^ 1;
            Ws[nbuf][cg*4+0][qr] = nw.x; Ws[nbuf][cg*4+1][qr] = nw.y;
            Ws[nbuf][cg*4+2][qr] = nw.z; Ws[nbuf][cg*4+3][qr] = nw.w;
            Cs[nbuf][cl][dl] = nc.x; Cs[nbuf][cl][dl+1] = nc.y;
        }
        __syncthreads();
        buf ^= 1;
    }

    #pragma unroll
    for (int i = 0; i < 4; i++) {
        float2 p = unpack2(acc[i]);
        const int q = ty * 4 + i;
        *(float2*)&out[(b * QQ + q) * DD + d0 + tx * 2] = p;
    }
}

// ---------------------------------------------------------------------------
extern "C" void kernel_launch(void* const* d_in, const int* in_sizes, int n_in,
                              void* d_out, int out_size)
{
    const float* query   = (const float*)d_in[0];
    const float* context = (const float*)d_in[1];
    const float* mask    = (const float*)d_in[2];
    const float* W_c     = (const float*)d_in[3];
    const float* b_c     = (const float*)d_in[4];
    const float* W_q     = (const float*)d_in[5];
    const float* W_o     = (const float*)d_in[6];
    const float* b_o     = (const float*)d_in[7];
    float* out = (float*)d_out;

    cudaFuncSetAttribute(tc_gemms, cudaFuncAttributeMaxDynamicSharedMemorySize,
                         TCG_SMEM);

    tc_gemms<<<144, 256, TCG_SMEM>>>(W_c, context, b_c, query, W_q);
    logits_softmax<<<256, 1024>>>(mask, W_o, b_o, out);
    out_gemm<<<128, 256>>>(context, out + WOFF, out);
}